// round 4
// baseline (speedup 1.0000x reference)
#include <cuda_runtime.h>
#include <math.h>

#define BATCH   2
#define LSEQ    2048
#define DMODEL  1024
#define DSTATE  128
#define DINNER  2048
#define HEADS   1024
#define PROJ    5376              // 2*DINNER + 2*DSTATE + DMODEL
#define ROWS    (BATCH*LSEQ)      // 4096

// offsets inside proj row
#define OFF_X   0
#define OFF_Z   DINNER            // 2048
#define OFF_B   (2*DINNER)        // 4096
#define OFF_C   (2*DINNER+DSTATE) // 4224
#define OFF_DT  (2*DINNER+2*DSTATE) // 4352

// ---------------- scratch (no allocation allowed) ----------------
__device__ float g_xn[(size_t)ROWS * DMODEL];      // 16 MB
__device__ float g_proj[(size_t)ROWS * PROJ];      // 88 MB
__device__ float g_decay[(size_t)ROWS * HEADS];    // 16 MB
__device__ float g_dtx[(size_t)ROWS * DINNER];     // 32 MB
__device__ float g_gate[(size_t)ROWS * DINNER];    // 32 MB

__device__ __forceinline__ float siluf(float x) {
    return x / (1.0f + expf(-x));
}
__device__ __forceinline__ float softplusf(float x) {
    return fmaxf(x, 0.0f) + log1pf(expf(-fabsf(x)));
}

// ---------------- layernorm: one block per row ----------------
__global__ void ln_kernel(const float* __restrict__ u,
                          const float* __restrict__ g,
                          const float* __restrict__ b) {
    int row = blockIdx.x;
    const float* x = u + (size_t)row * DMODEL;
    float*       o = g_xn + (size_t)row * DMODEL;
    float s = 0.f, ss = 0.f;
    for (int i = threadIdx.x; i < DMODEL; i += 256) {
        float v = x[i];
        s += v; ss += v * v;
    }
    __shared__ float sh0[8], sh1[8];
    #pragma unroll
    for (int off = 16; off; off >>= 1) {
        s  += __shfl_xor_sync(0xffffffffu, s,  off);
        ss += __shfl_xor_sync(0xffffffffu, ss, off);
    }
    if ((threadIdx.x & 31) == 0) { sh0[threadIdx.x >> 5] = s; sh1[threadIdx.x >> 5] = ss; }
    __syncthreads();
    if (threadIdx.x < 32) {
        s  = (threadIdx.x < 8) ? sh0[threadIdx.x] : 0.f;
        ss = (threadIdx.x < 8) ? sh1[threadIdx.x] : 0.f;
        #pragma unroll
        for (int off = 4; off; off >>= 1) {
            s  += __shfl_xor_sync(0xffffffffu, s,  off);
            ss += __shfl_xor_sync(0xffffffffu, ss, off);
        }
        if (threadIdx.x == 0) { sh0[0] = s; sh1[0] = ss; }
    }
    __syncthreads();
    float mean = sh0[0] * (1.0f / DMODEL);
    float var  = sh1[0] * (1.0f / DMODEL) - mean * mean;
    float inv  = rsqrtf(var + 1e-5f);
    for (int i = threadIdx.x; i < DMODEL; i += 256) {
        o[i] = (x[i] - mean) * inv * g[i] + b[i];
    }
}

// ---------------- classic 128x128x8 fp32 SGEMM, 256 threads ----------------
// C[M,N] = A[M,K] @ B[K,N]  (+ ADD if WITH_ADD), all row-major,
// M%128==0, N%128==0, K%8==0, N%4==0, K%4==0.
template <int WITH_ADD>
__global__ void __launch_bounds__(256, 2)
sgemm128(const float* __restrict__ A, const float* __restrict__ B,
         float* __restrict__ C, const float* __restrict__ ADD,
         int M, int N, int K) {
    __shared__ float As[8][128];
    __shared__ float Bs[8][128];
    int tid = threadIdx.x;
    const float* Ab = A + (size_t)blockIdx.y * 128 * K;
    const float* Bb = B + (size_t)blockIdx.x * 128;

    int arow = tid >> 1, acol = (tid & 1) * 4;
    int brow = tid >> 5, bcol = (tid & 31) * 4;
    int tx = (tid & 15) * 8;
    int ty = (tid >> 4) * 8;

    float acc[8][8];
    #pragma unroll
    for (int i = 0; i < 8; i++)
        #pragma unroll
        for (int j = 0; j < 8; j++) acc[i][j] = 0.f;

    for (int k0 = 0; k0 < K; k0 += 8) {
        float4 av = *(const float4*)(Ab + (size_t)arow * K + k0 + acol);
        As[acol + 0][arow] = av.x;
        As[acol + 1][arow] = av.y;
        As[acol + 2][arow] = av.z;
        As[acol + 3][arow] = av.w;
        float4 bv = *(const float4*)(Bb + (size_t)(k0 + brow) * N + bcol);
        *(float4*)&Bs[brow][bcol] = bv;
        __syncthreads();
        #pragma unroll
        for (int kk = 0; kk < 8; kk++) {
            float ar[8], br[8];
            #pragma unroll
            for (int i = 0; i < 8; i++) ar[i] = As[kk][ty + i];
            #pragma unroll
            for (int j = 0; j < 8; j++) br[j] = Bs[kk][tx + j];
            #pragma unroll
            for (int i = 0; i < 8; i++)
                #pragma unroll
                for (int j = 0; j < 8; j++)
                    acc[i][j] = fmaf(ar[i], br[j], acc[i][j]);
        }
        __syncthreads();
    }

    #pragma unroll
    for (int i = 0; i < 8; i++) {
        size_t row = (size_t)blockIdx.y * 128 + ty + i;
        float* cp = C + row * N + (size_t)blockIdx.x * 128 + tx;
        if (WITH_ADD) {
            const float* ap = ADD + row * N + (size_t)blockIdx.x * 128 + tx;
            #pragma unroll
            for (int j = 0; j < 8; j += 4) {
                float4 a4 = *(const float4*)(ap + j);
                float4 v;
                v.x = acc[i][j + 0] + a4.x;
                v.y = acc[i][j + 1] + a4.y;
                v.z = acc[i][j + 2] + a4.z;
                v.w = acc[i][j + 3] + a4.w;
                *(float4*)(cp + j) = v;
            }
        } else {
            #pragma unroll
            for (int j = 0; j < 8; j += 4) {
                float4 v;
                v.x = acc[i][j + 0];
                v.y = acc[i][j + 1];
                v.z = acc[i][j + 2];
                v.w = acc[i][j + 3];
                *(float4*)(cp + j) = v;
            }
        }
    }
}

// ---------------- conv + silu + softplus(dt) + decay + dtx ----------------
// one block per (b,t) row
__global__ void conv_dt_kernel(const float* __restrict__ conv_w,
                               const float* __restrict__ conv_b,
                               const float* __restrict__ A_log) {
    int row = blockIdx.x;
    int t = row & (LSEQ - 1);
    size_t base = (size_t)row * PROJ;

    // depthwise causal conv over x channels + silu, then dtx = softplus(dt)*silu(conv(x))
    for (int c = threadIdx.x; c < DINNER; c += 256) {
        float acc = conv_b[c];
        #pragma unroll
        for (int k = 0; k < 4; k++) {
            int tt = t - 3 + k;
            if (tt >= 0)
                acc = fmaf(conv_w[c * 4 + k], g_proj[base + (size_t)(k - 3) * PROJ + c], acc);
        }
        float xs = siluf(acc);
        int h = c >> 1;
        float dts = softplusf(g_proj[base + OFF_DT + h]);
        g_dtx[(size_t)row * DINNER + c] = dts * xs;
    }
    // per-head decay
    for (int h = threadIdx.x; h < HEADS; h += 256) {
        float dts = softplusf(g_proj[base + OFF_DT + h]);
        float A = -expf(A_log[h]);
        g_decay[(size_t)row * HEADS + h] = expf(dts * A);
    }
}

// ---------------- selective scan: one warp per (b,h) ----------------
// lanes 0-15: p=0, lanes 16-31: p=1; each lane holds 8 states (n = (lane&15)*8 .. +7)
__global__ void __launch_bounds__(128, 8) scan_kernel() {
    int w    = blockIdx.x * 4 + (threadIdx.x >> 5);
    int b    = w >> 10;          // / HEADS
    int h    = w & (HEADS - 1);
    int lane = threadIdx.x & 31;
    int p    = lane >> 4;
    int j0   = (lane & 15) * 8;

    float S[8];
    #pragma unroll
    for (int i = 0; i < 8; i++) S[i] = 0.f;

    size_t rowBase = (size_t)b * LSEQ;
    #pragma unroll 2
    for (int t = 0; t < LSEQ; t++) {
        size_t row = rowBase + t;
        size_t pb  = row * PROJ;
        float dec = g_decay[row * HEADS + h];
        float cx  = g_dtx[row * DINNER + h * 2 + p];
        float4 b0 = *(const float4*)(g_proj + pb + OFF_B + j0);
        float4 b1 = *(const float4*)(g_proj + pb + OFF_B + j0 + 4);
        float4 c0 = *(const float4*)(g_proj + pb + OFF_C + j0);
        float4 c1 = *(const float4*)(g_proj + pb + OFF_C + j0 + 4);

        float y = 0.f;
        S[0] = fmaf(dec, S[0], cx * b0.x); y = fmaf(S[0], c0.x, y);
        S[1] = fmaf(dec, S[1], cx * b0.y); y = fmaf(S[1], c0.y, y);
        S[2] = fmaf(dec, S[2], cx * b0.z); y = fmaf(S[2], c0.z, y);
        S[3] = fmaf(dec, S[3], cx * b0.w); y = fmaf(S[3], c0.w, y);
        S[4] = fmaf(dec, S[4], cx * b1.x); y = fmaf(S[4], c1.x, y);
        S[5] = fmaf(dec, S[5], cx * b1.y); y = fmaf(S[5], c1.y, y);
        S[6] = fmaf(dec, S[6], cx * b1.z); y = fmaf(S[6], c1.z, y);
        S[7] = fmaf(dec, S[7], cx * b1.w); y = fmaf(S[7], c1.w, y);

        // reduce over the 16 lanes of this p-half
        y += __shfl_xor_sync(0xffffffffu, y, 1);
        y += __shfl_xor_sync(0xffffffffu, y, 2);
        y += __shfl_xor_sync(0xffffffffu, y, 4);
        y += __shfl_xor_sync(0xffffffffu, y, 8);

        if ((lane & 15) == 0) {
            float z = g_proj[pb + OFF_Z + h * 2 + p];
            g_gate[row * DINNER + h * 2 + p] = y * siluf(z);
        }
    }
}

// ---------------- launch ----------------
extern "C" void kernel_launch(void* const* d_in, const int* in_sizes, int n_in,
                              void* d_out, int out_size) {
    const float* u      = (const float*)d_in[0];
    const float* W_in   = (const float*)d_in[1];
    const float* conv_w = (const float*)d_in[2];
    const float* conv_b = (const float*)d_in[3];
    const float* W_out  = (const float*)d_in[4];
    const float* ln_g   = (const float*)d_in[5];
    const float* ln_b   = (const float*)d_in[6];
    const float* A_log  = (const float*)d_in[7];
    float* out = (float*)d_out;

    float *p_xn, *p_proj, *p_gate;
    cudaGetSymbolAddress((void**)&p_xn,   g_xn);
    cudaGetSymbolAddress((void**)&p_proj, g_proj);
    cudaGetSymbolAddress((void**)&p_gate, g_gate);

    // 1. layernorm
    ln_kernel<<<ROWS, 256>>>(u, ln_g, ln_b);

    // 2. big projection GEMM: (4096,1024) @ (1024,5376)
    {
        dim3 grid(PROJ / 128, ROWS / 128);
        sgemm128<0><<<grid, 256>>>(p_xn, W_in, p_proj, nullptr, ROWS, PROJ, DMODEL);
    }

    // 3. conv + dt/decay/dtx
    conv_dt_kernel<<<ROWS, 256>>>(conv_w, conv_b, A_log);

    // 4. selective scan + output gating
    scan_kernel<<<(BATCH * HEADS) / 4, 128>>>();

    // 5. out = u + gate @ W_out : (4096,2048) @ (2048,1024)
    {
        dim3 grid(DMODEL / 128, ROWS / 128);
        sgemm128<1><<<grid, 256>>>(p_gate, W_out, out, u, ROWS, DMODEL, DINNER);
    }
}

// round 15
// speedup vs baseline: 1.3268x; 1.3268x over previous
#include <cuda_runtime.h>
#include <cuda_bf16.h>
#include <stdint.h>
#include <cstdint>
#include <math.h>

#define BATCH   2
#define LSEQ    2048
#define DMODEL  1024
#define DSTATE  128
#define DINNER  2048
#define HEADS   1024
#define PROJ    5376              // 2*DINNER + 2*DSTATE + DMODEL
#define ROWS    (BATCH*LSEQ)      // 4096

#define OFF_X   0
#define OFF_Z   DINNER
#define OFF_B   (2*DINNER)
#define OFF_C   (2*DINNER+DSTATE)
#define OFF_DT  (2*DINNER+2*DSTATE)

// ---------------- scratch ----------------
__device__ float g_proj[(size_t)ROWS * PROJ];      // 88 MB
__device__ float g_decay[(size_t)ROWS * HEADS];
__device__ float g_dtx[(size_t)ROWS * DINNER];
__device__ __nv_bfloat16 g_xn_h[(size_t)ROWS * DMODEL];
__device__ __nv_bfloat16 g_xn_l[(size_t)ROWS * DMODEL];
__device__ __nv_bfloat16 g_gate_h[(size_t)ROWS * DINNER];
__device__ __nv_bfloat16 g_gate_l[(size_t)ROWS * DINNER];
__device__ __nv_bfloat16 g_win_h[(size_t)DMODEL * PROJ];
__device__ __nv_bfloat16 g_win_l[(size_t)DMODEL * PROJ];
__device__ __nv_bfloat16 g_wout_h[(size_t)DINNER * DMODEL];
__device__ __nv_bfloat16 g_wout_l[(size_t)DINNER * DMODEL];

__device__ __forceinline__ float siluf(float x) { return x / (1.0f + expf(-x)); }
__device__ __forceinline__ float softplusf(float x) {
    return fmaxf(x, 0.0f) + log1pf(expf(-fabsf(x)));
}
__device__ __forceinline__ void split_bf16(float x, __nv_bfloat16& h, __nv_bfloat16& l) {
    h = __float2bfloat16(x);
    l = __float2bfloat16(x - __bfloat162float(h));
}

// ---------------- weight split ----------------
__global__ void split_kernel(const float* __restrict__ src,
                             __nv_bfloat16* __restrict__ h,
                             __nv_bfloat16* __restrict__ l, int n) {
    int i = blockIdx.x * 256 + threadIdx.x;
    if (i < n) {
        __nv_bfloat16 hi, lo;
        split_bf16(src[i], hi, lo);
        h[i] = hi; l[i] = lo;
    }
}

// ---------------- layernorm -> bf16 hi/lo ----------------
__global__ void ln_kernel(const float* __restrict__ u,
                          const float* __restrict__ g,
                          const float* __restrict__ b) {
    int row = blockIdx.x;
    const float* x = u + (size_t)row * DMODEL;
    float s = 0.f, ss = 0.f;
    for (int i = threadIdx.x; i < DMODEL; i += 256) {
        float v = x[i];
        s += v; ss += v * v;
    }
    __shared__ float sh0[8], sh1[8];
    #pragma unroll
    for (int off = 16; off; off >>= 1) {
        s  += __shfl_xor_sync(0xffffffffu, s,  off);
        ss += __shfl_xor_sync(0xffffffffu, ss, off);
    }
    if ((threadIdx.x & 31) == 0) { sh0[threadIdx.x >> 5] = s; sh1[threadIdx.x >> 5] = ss; }
    __syncthreads();
    if (threadIdx.x < 32) {
        s  = (threadIdx.x < 8) ? sh0[threadIdx.x] : 0.f;
        ss = (threadIdx.x < 8) ? sh1[threadIdx.x] : 0.f;
        #pragma unroll
        for (int off = 4; off; off >>= 1) {
            s  += __shfl_xor_sync(0xffffffffu, s,  off);
            ss += __shfl_xor_sync(0xffffffffu, ss, off);
        }
        if (threadIdx.x == 0) { sh0[0] = s; sh1[0] = ss; }
    }
    __syncthreads();
    float mean = sh0[0] * (1.0f / DMODEL);
    float var  = sh1[0] * (1.0f / DMODEL) - mean * mean;
    float inv  = rsqrtf(var + 1e-5f);
    size_t base = (size_t)row * DMODEL;
    for (int i = threadIdx.x; i < DMODEL; i += 256) {
        float v = (x[i] - mean) * inv * g[i] + b[i];
        __nv_bfloat16 hi, lo;
        split_bf16(v, hi, lo);
        g_xn_h[base + i] = hi;
        g_xn_l[base + i] = lo;
    }
}

// ---------------- tensor-core GEMM (bf16 3-term split, fp32 acc) ----------------
__device__ __forceinline__ uint32_t smem_u32(const void* p) {
    return (uint32_t)__cvta_generic_to_shared(p);
}
__device__ __forceinline__ void ldm_x4(uint32_t* r, uint32_t addr) {
    asm volatile("ldmatrix.sync.aligned.m8n8.x4.shared.b16 {%0,%1,%2,%3}, [%4];\n"
        : "=r"(r[0]), "=r"(r[1]), "=r"(r[2]), "=r"(r[3]) : "r"(addr));
}
__device__ __forceinline__ void ldm_x4_t(uint32_t* r, uint32_t addr) {
    asm volatile("ldmatrix.sync.aligned.m8n8.x4.trans.shared.b16 {%0,%1,%2,%3}, [%4];\n"
        : "=r"(r[0]), "=r"(r[1]), "=r"(r[2]), "=r"(r[3]) : "r"(addr));
}
__device__ __forceinline__ void mma16816(float* d, const uint32_t* a, const uint32_t* b) {
    asm volatile(
        "mma.sync.aligned.m16n8k16.row.col.f32.bf16.bf16.f32 "
        "{%0,%1,%2,%3}, {%4,%5,%6,%7}, {%8,%9}, {%0,%1,%2,%3};\n"
        : "+f"(d[0]), "+f"(d[1]), "+f"(d[2]), "+f"(d[3])
        : "r"(a[0]), "r"(a[1]), "r"(a[2]), "r"(a[3]), "r"(b[0]), "r"(b[1]));
}

// C[M,N] = (Ah+Al)[M,K] @ (Bh+Bl)[K,N] (+ADD), row-major. 128x128 tile, 256 thr.
template <int WITH_ADD>
__global__ void __launch_bounds__(256)
gemm_bf16(const __nv_bfloat16* __restrict__ Ah, const __nv_bfloat16* __restrict__ Al,
          const __nv_bfloat16* __restrict__ Bh, const __nv_bfloat16* __restrict__ Bl,
          float* __restrict__ C, const float* __restrict__ ADD,
          int M, int N, int K) {
    __shared__ __nv_bfloat16 sA[2][128][40];   // [hi/lo][m][k], stride 40 (80B)
    __shared__ __nv_bfloat16 sB[2][32][136];   // [hi/lo][k][n], stride 136 (272B)

    int tid = threadIdx.x, lane = tid & 31, warp = tid >> 5;
    int wm = warp >> 1, wn = warp & 1;                 // 4x2 warps
    int bm = blockIdx.y, bn = blockIdx.x;

    float acc[2][8][4];
    #pragma unroll
    for (int i = 0; i < 2; i++) {
        #pragma unroll
        for (int j = 0; j < 8; j++) {
            #pragma unroll
            for (int k = 0; k < 4; k++) acc[i][j][k] = 0.f;
        }
    }

    int row_a = tid >> 2, col_a = (tid & 3) * 8;       // A: 64 rows/iter
    int row_b = tid >> 4, col_b = (tid & 15) * 8;      // B: 16 krows/iter
    int sub = lane >> 3, r8 = lane & 7;

    for (int k0 = 0; k0 < K; k0 += 32) {
        #pragma unroll
        for (int it = 0; it < 2; it++) {
            int r = row_a + it * 64;
            size_t ga = (size_t)(bm * 128 + r) * K + k0 + col_a;
            *(uint4*)&sA[0][r][col_a] = *(const uint4*)(Ah + ga);
            *(uint4*)&sA[1][r][col_a] = *(const uint4*)(Al + ga);
            int kr = row_b + it * 16;
            size_t gb = (size_t)(k0 + kr) * N + bn * 128 + col_b;
            *(uint4*)&sB[0][kr][col_b] = *(const uint4*)(Bh + gb);
            *(uint4*)&sB[1][kr][col_b] = *(const uint4*)(Bl + gb);
        }
        __syncthreads();

        #pragma unroll
        for (int ks = 0; ks < 2; ks++) {
            int kb = ks * 16;
            int arow = ((sub & 1) << 3) + r8;
            int acol = kb + ((sub >> 1) << 3);
            int brow = kb + ((sub & 1) << 3) + r8;
            int bcol = ((sub >> 1) << 3);

            uint32_t ah[2][4], bh[8][2], bl[8][2];
            #pragma unroll
            for (int mi = 0; mi < 2; mi++) {
                ldm_x4(ah[mi], smem_u32(&sA[0][wm * 32 + mi * 16 + arow][acol]));
            }
            #pragma unroll
            for (int pr = 0; pr < 4; pr++) {
                int n0 = wn * 64 + pr * 16 + bcol;
                uint32_t t[4];
                ldm_x4_t(t, smem_u32(&sB[0][brow][n0]));
                bh[2*pr][0] = t[0]; bh[2*pr][1] = t[1];
                bh[2*pr+1][0] = t[2]; bh[2*pr+1][1] = t[3];
                ldm_x4_t(t, smem_u32(&sB[1][brow][n0]));
                bl[2*pr][0] = t[0]; bl[2*pr][1] = t[1];
                bl[2*pr+1][0] = t[2]; bl[2*pr+1][1] = t[3];
            }
            #pragma unroll
            for (int mi = 0; mi < 2; mi++) {
                #pragma unroll
                for (int ni = 0; ni < 8; ni++) {
                    mma16816(acc[mi][ni], ah[mi], bh[ni]);
                    mma16816(acc[mi][ni], ah[mi], bl[ni]);
                }
            }
            uint32_t al[2][4];
            #pragma unroll
            for (int mi = 0; mi < 2; mi++) {
                ldm_x4(al[mi], smem_u32(&sA[1][wm * 32 + mi * 16 + arow][acol]));
            }
            #pragma unroll
            for (int mi = 0; mi < 2; mi++) {
                #pragma unroll
                for (int ni = 0; ni < 8; ni++) {
                    mma16816(acc[mi][ni], al[mi], bh[ni]);
                }
            }
        }
        __syncthreads();
    }

    int g = lane >> 2, tg = lane & 3;
    #pragma unroll
    for (int mi = 0; mi < 2; mi++) {
        #pragma unroll
        for (int ni = 0; ni < 8; ni++) {
            size_t row0 = (size_t)bm * 128 + wm * 32 + mi * 16 + g;
            size_t col  = (size_t)bn * 128 + wn * 64 + ni * 8 + tg * 2;
            float2 v0 = make_float2(acc[mi][ni][0], acc[mi][ni][1]);
            float2 v1 = make_float2(acc[mi][ni][2], acc[mi][ni][3]);
            if (WITH_ADD) {
                float2 a0 = *(const float2*)(ADD + row0 * N + col);
                float2 a1 = *(const float2*)(ADD + (row0 + 8) * N + col);
                v0.x += a0.x; v0.y += a0.y; v1.x += a1.x; v1.y += a1.y;
            }
            *(float2*)(C + row0 * N + col) = v0;
            *(float2*)(C + (row0 + 8) * N + col) = v1;
        }
    }
}

// ---------------- conv + silu + softplus(dt) + decay + dtx ----------------
__global__ void conv_dt_kernel(const float* __restrict__ conv_w,
                               const float* __restrict__ conv_b,
                               const float* __restrict__ A_log) {
    int row = blockIdx.x;
    int t = row & (LSEQ - 1);
    size_t base = (size_t)row * PROJ;

    for (int c = threadIdx.x; c < DINNER; c += 256) {
        float acc = conv_b[c];
        #pragma unroll
        for (int k = 0; k < 4; k++) {
            int tt = t - 3 + k;
            if (tt >= 0)
                acc = fmaf(conv_w[c * 4 + k], g_proj[base + (size_t)(k - 3) * PROJ + c], acc);
        }
        float xs = siluf(acc);
        int h = c >> 1;
        float dts = softplusf(g_proj[base + OFF_DT + h]);
        g_dtx[(size_t)row * DINNER + c] = dts * xs;
    }
    for (int h = threadIdx.x; h < HEADS; h += 256) {
        float dts = softplusf(g_proj[base + OFF_DT + h]);
        float A = -expf(A_log[h]);
        g_decay[(size_t)row * HEADS + h] = expf(dts * A);
    }
}

// ---------------- selective scan ----------------
__global__ void __launch_bounds__(128, 8) scan_kernel() {
    int w    = blockIdx.x * 4 + (threadIdx.x >> 5);
    int b    = w >> 10;
    int h    = w & (HEADS - 1);
    int lane = threadIdx.x & 31;
    int p    = lane >> 4;
    int j0   = (lane & 15) * 8;

    float S[8];
    #pragma unroll
    for (int i = 0; i < 8; i++) S[i] = 0.f;

    size_t rowBase = (size_t)b * LSEQ;
    #pragma unroll 2
    for (int t = 0; t < LSEQ; t++) {
        size_t row = rowBase + t;
        size_t pb  = row * PROJ;
        float dec = g_decay[row * HEADS + h];
        float cx  = g_dtx[row * DINNER + h * 2 + p];
        float4 b0 = *(const float4*)(g_proj + pb + OFF_B + j0);
        float4 b1 = *(const float4*)(g_proj + pb + OFF_B + j0 + 4);
        float4 c0 = *(const float4*)(g_proj + pb + OFF_C + j0);
        float4 c1 = *(const float4*)(g_proj + pb + OFF_C + j0 + 4);

        float y = 0.f;
        S[0] = fmaf(dec, S[0], cx * b0.x); y = fmaf(S[0], c0.x, y);
        S[1] = fmaf(dec, S[1], cx * b0.y); y = fmaf(S[1], c0.y, y);
        S[2] = fmaf(dec, S[2], cx * b0.z); y = fmaf(S[2], c0.z, y);
        S[3] = fmaf(dec, S[3], cx * b0.w); y = fmaf(S[3], c0.w, y);
        S[4] = fmaf(dec, S[4], cx * b1.x); y = fmaf(S[4], c1.x, y);
        S[5] = fmaf(dec, S[5], cx * b1.y); y = fmaf(S[5], c1.y, y);
        S[6] = fmaf(dec, S[6], cx * b1.z); y = fmaf(S[6], c1.z, y);
        S[7] = fmaf(dec, S[7], cx * b1.w); y = fmaf(S[7], c1.w, y);

        y += __shfl_xor_sync(0xffffffffu, y, 1);
        y += __shfl_xor_sync(0xffffffffu, y, 2);
        y += __shfl_xor_sync(0xffffffffu, y, 4);
        y += __shfl_xor_sync(0xffffffffu, y, 8);

        if ((lane & 15) == 0) {
            float z = g_proj[pb + OFF_Z + h * 2 + p];
            float gv = y * siluf(z);
            __nv_bfloat16 hi, lo;
            split_bf16(gv, hi, lo);
            size_t idx = row * DINNER + h * 2 + p;
            g_gate_h[idx] = hi;
            g_gate_l[idx] = lo;
        }
    }
}

// ---------------- launch ----------------
extern "C" void kernel_launch(void* const* d_in, const int* in_sizes, int n_in,
                              void* d_out, int out_size) {
    const float* u      = (const float*)d_in[0];
    const float* W_in   = (const float*)d_in[1];
    const float* conv_w = (const float*)d_in[2];
    const float* conv_b = (const float*)d_in[3];
    const float* W_out  = (const float*)d_in[4];
    const float* ln_g   = (const float*)d_in[5];
    const float* ln_b   = (const float*)d_in[6];
    const float* A_log  = (const float*)d_in[7];
    float* out = (float*)d_out;

    float* p_proj;
    __nv_bfloat16 *p_xn_h, *p_xn_l, *p_gate_h, *p_gate_l;
    __nv_bfloat16 *p_win_h, *p_win_l, *p_wout_h, *p_wout_l;
    cudaGetSymbolAddress((void**)&p_proj,   g_proj);
    cudaGetSymbolAddress((void**)&p_xn_h,   g_xn_h);
    cudaGetSymbolAddress((void**)&p_xn_l,   g_xn_l);
    cudaGetSymbolAddress((void**)&p_gate_h, g_gate_h);
    cudaGetSymbolAddress((void**)&p_gate_l, g_gate_l);
    cudaGetSymbolAddress((void**)&p_win_h,  g_win_h);
    cudaGetSymbolAddress((void**)&p_win_l,  g_win_l);
    cudaGetSymbolAddress((void**)&p_wout_h, g_wout_h);
    cudaGetSymbolAddress((void**)&p_wout_l, g_wout_l);

    // weight splits
    {
        int n1 = DMODEL * PROJ;
        split_kernel<<<(n1 + 255) / 256, 256>>>(W_in, p_win_h, p_win_l, n1);
        int n2 = DINNER * DMODEL;
        split_kernel<<<(n2 + 255) / 256, 256>>>(W_out, p_wout_h, p_wout_l, n2);
    }

    // 1. layernorm -> bf16 hi/lo
    ln_kernel<<<ROWS, 256>>>(u, ln_g, ln_b);

    // 2. proj = xn @ W_in : (4096,1024)@(1024,5376)
    {
        dim3 grid(PROJ / 128, ROWS / 128);
        gemm_bf16<0><<<grid, 256>>>(p_xn_h, p_xn_l, p_win_h, p_win_l,
                                    p_proj, nullptr, ROWS, PROJ, DMODEL);
    }

    // 3. conv + dt/decay/dtx
    conv_dt_kernel<<<ROWS, 256>>>(conv_w, conv_b, A_log);

    // 4. selective scan + gating -> bf16 hi/lo
    scan_kernel<<<(BATCH * HEADS) / 4, 128>>>();

    // 5. out = u + gate @ W_out : (4096,2048)@(2048,1024)
    {
        dim3 grid(DMODEL / 128, ROWS / 128);
        gemm_bf16<1><<<grid, 256>>>(p_gate_h, p_gate_l, p_wout_h, p_wout_l,
                                    out, u, ROWS, DMODEL, DINNER);
    }
}

// round 16
// speedup vs baseline: 2.0784x; 1.5665x over previous
#include <cuda_runtime.h>
#include <cuda_bf16.h>
#include <stdint.h>
#include <cstdint>
#include <math.h>

#define BATCH   2
#define LSEQ    2048
#define DMODEL  1024
#define DSTATE  128
#define DINNER  2048
#define HEADS   1024
#define PROJ    5376              // 2*DINNER + 2*DSTATE + DMODEL
#define ROWS    (BATCH*LSEQ)      // 4096
#define TCHUNK  128
#define NCHUNK  (LSEQ / TCHUNK)   // 16

#define OFF_X   0
#define OFF_Z   DINNER
#define OFF_B   (2*DINNER)
#define OFF_C   (2*DINNER+DSTATE)
#define OFF_DT  (2*DINNER+2*DSTATE)

// ---------------- scratch ----------------
__device__ float g_proj[(size_t)ROWS * PROJ];      // 88 MB
__device__ float g_decay[(size_t)ROWS * HEADS];
__device__ float g_dtx[(size_t)ROWS * DINNER];
__device__ float g_state[(size_t)BATCH * HEADS * NCHUNK * 256];  // 33.5 MB
__device__ float g_dprod[(size_t)BATCH * HEADS * NCHUNK];
__device__ __nv_bfloat16 g_xn_h[(size_t)ROWS * DMODEL];
__device__ __nv_bfloat16 g_xn_l[(size_t)ROWS * DMODEL];
__device__ __nv_bfloat16 g_gate_h[(size_t)ROWS * DINNER];
__device__ __nv_bfloat16 g_gate_l[(size_t)ROWS * DINNER];
__device__ __nv_bfloat16 g_win_h[(size_t)DMODEL * PROJ];
__device__ __nv_bfloat16 g_win_l[(size_t)DMODEL * PROJ];
__device__ __nv_bfloat16 g_wout_h[(size_t)DINNER * DMODEL];
__device__ __nv_bfloat16 g_wout_l[(size_t)DINNER * DMODEL];

__device__ __forceinline__ float siluf(float x) { return x / (1.0f + expf(-x)); }
__device__ __forceinline__ float softplusf(float x) {
    return fmaxf(x, 0.0f) + log1pf(expf(-fabsf(x)));
}
__device__ __forceinline__ void split_bf16(float x, __nv_bfloat16& h, __nv_bfloat16& l) {
    h = __float2bfloat16(x);
    l = __float2bfloat16(x - __bfloat162float(h));
}

// ---------------- weight split ----------------
__global__ void split_kernel(const float* __restrict__ src,
                             __nv_bfloat16* __restrict__ h,
                             __nv_bfloat16* __restrict__ l, int n) {
    int i = blockIdx.x * 256 + threadIdx.x;
    if (i < n) {
        __nv_bfloat16 hi, lo;
        split_bf16(src[i], hi, lo);
        h[i] = hi; l[i] = lo;
    }
}

// ---------------- layernorm -> bf16 hi/lo ----------------
__global__ void ln_kernel(const float* __restrict__ u,
                          const float* __restrict__ g,
                          const float* __restrict__ b) {
    int row = blockIdx.x;
    const float* x = u + (size_t)row * DMODEL;
    float s = 0.f, ss = 0.f;
    for (int i = threadIdx.x; i < DMODEL; i += 256) {
        float v = x[i];
        s += v; ss += v * v;
    }
    __shared__ float sh0[8], sh1[8];
    #pragma unroll
    for (int off = 16; off; off >>= 1) {
        s  += __shfl_xor_sync(0xffffffffu, s,  off);
        ss += __shfl_xor_sync(0xffffffffu, ss, off);
    }
    if ((threadIdx.x & 31) == 0) { sh0[threadIdx.x >> 5] = s; sh1[threadIdx.x >> 5] = ss; }
    __syncthreads();
    if (threadIdx.x < 32) {
        s  = (threadIdx.x < 8) ? sh0[threadIdx.x] : 0.f;
        ss = (threadIdx.x < 8) ? sh1[threadIdx.x] : 0.f;
        #pragma unroll
        for (int off = 4; off; off >>= 1) {
            s  += __shfl_xor_sync(0xffffffffu, s,  off);
            ss += __shfl_xor_sync(0xffffffffu, ss, off);
        }
        if (threadIdx.x == 0) { sh0[0] = s; sh1[0] = ss; }
    }
    __syncthreads();
    float mean = sh0[0] * (1.0f / DMODEL);
    float var  = sh1[0] * (1.0f / DMODEL) - mean * mean;
    float inv  = rsqrtf(var + 1e-5f);
    size_t base = (size_t)row * DMODEL;
    for (int i = threadIdx.x; i < DMODEL; i += 256) {
        float v = (x[i] - mean) * inv * g[i] + b[i];
        __nv_bfloat16 hi, lo;
        split_bf16(v, hi, lo);
        g_xn_h[base + i] = hi;
        g_xn_l[base + i] = lo;
    }
}

// ---------------- tensor-core GEMM (bf16 3-term split, fp32 acc) ----------------
__device__ __forceinline__ uint32_t smem_u32(const void* p) {
    return (uint32_t)__cvta_generic_to_shared(p);
}
__device__ __forceinline__ void ldm_x4(uint32_t* r, uint32_t addr) {
    asm volatile("ldmatrix.sync.aligned.m8n8.x4.shared.b16 {%0,%1,%2,%3}, [%4];\n"
        : "=r"(r[0]), "=r"(r[1]), "=r"(r[2]), "=r"(r[3]) : "r"(addr));
}
__device__ __forceinline__ void ldm_x4_t(uint32_t* r, uint32_t addr) {
    asm volatile("ldmatrix.sync.aligned.m8n8.x4.trans.shared.b16 {%0,%1,%2,%3}, [%4];\n"
        : "=r"(r[0]), "=r"(r[1]), "=r"(r[2]), "=r"(r[3]) : "r"(addr));
}
__device__ __forceinline__ void mma16816(float* d, const uint32_t* a, const uint32_t* b) {
    asm volatile(
        "mma.sync.aligned.m16n8k16.row.col.f32.bf16.bf16.f32 "
        "{%0,%1,%2,%3}, {%4,%5,%6,%7}, {%8,%9}, {%0,%1,%2,%3};\n"
        : "+f"(d[0]), "+f"(d[1]), "+f"(d[2]), "+f"(d[3])
        : "r"(a[0]), "r"(a[1]), "r"(a[2]), "r"(a[3]), "r"(b[0]), "r"(b[1]));
}

// C[M,N] = (Ah+Al)[M,K] @ (Bh+Bl)[K,N] (+ADD), row-major. 128x128 tile, 256 thr.
template <int WITH_ADD>
__global__ void __launch_bounds__(256)
gemm_bf16(const __nv_bfloat16* __restrict__ Ah, const __nv_bfloat16* __restrict__ Al,
          const __nv_bfloat16* __restrict__ Bh, const __nv_bfloat16* __restrict__ Bl,
          float* __restrict__ C, const float* __restrict__ ADD,
          int M, int N, int K) {
    __shared__ __nv_bfloat16 sA[2][128][40];   // [hi/lo][m][k], stride 40 (80B)
    __shared__ __nv_bfloat16 sB[2][32][136];   // [hi/lo][k][n], stride 136 (272B)

    int tid = threadIdx.x, lane = tid & 31, warp = tid >> 5;
    int wm = warp >> 1, wn = warp & 1;                 // 4x2 warps
    int bm = blockIdx.y, bn = blockIdx.x;

    float acc[2][8][4];
    #pragma unroll
    for (int i = 0; i < 2; i++) {
        #pragma unroll
        for (int j = 0; j < 8; j++) {
            #pragma unroll
            for (int k = 0; k < 4; k++) acc[i][j][k] = 0.f;
        }
    }

    int row_a = tid >> 2, col_a = (tid & 3) * 8;       // A: 64 rows/iter
    int row_b = tid >> 4, col_b = (tid & 15) * 8;      // B: 16 krows/iter
    int sub = lane >> 3, r8 = lane & 7;

    for (int k0 = 0; k0 < K; k0 += 32) {
        #pragma unroll
        for (int it = 0; it < 2; it++) {
            int r = row_a + it * 64;
            size_t ga = (size_t)(bm * 128 + r) * K + k0 + col_a;
            *(uint4*)&sA[0][r][col_a] = *(const uint4*)(Ah + ga);
            *(uint4*)&sA[1][r][col_a] = *(const uint4*)(Al + ga);
            int kr = row_b + it * 16;
            size_t gb = (size_t)(k0 + kr) * N + bn * 128 + col_b;
            *(uint4*)&sB[0][kr][col_b] = *(const uint4*)(Bh + gb);
            *(uint4*)&sB[1][kr][col_b] = *(const uint4*)(Bl + gb);
        }
        __syncthreads();

        #pragma unroll
        for (int ks = 0; ks < 2; ks++) {
            int kb = ks * 16;
            int arow = ((sub & 1) << 3) + r8;
            int acol = kb + ((sub >> 1) << 3);
            int brow = kb + ((sub & 1) << 3) + r8;
            int bcol = ((sub >> 1) << 3);

            uint32_t ah[2][4], bh[8][2], bl[8][2];
            #pragma unroll
            for (int mi = 0; mi < 2; mi++) {
                ldm_x4(ah[mi], smem_u32(&sA[0][wm * 32 + mi * 16 + arow][acol]));
            }
            #pragma unroll
            for (int pr = 0; pr < 4; pr++) {
                int n0 = wn * 64 + pr * 16 + bcol;
                uint32_t t[4];
                ldm_x4_t(t, smem_u32(&sB[0][brow][n0]));
                bh[2*pr][0] = t[0]; bh[2*pr][1] = t[1];
                bh[2*pr+1][0] = t[2]; bh[2*pr+1][1] = t[3];
                ldm_x4_t(t, smem_u32(&sB[1][brow][n0]));
                bl[2*pr][0] = t[0]; bl[2*pr][1] = t[1];
                bl[2*pr+1][0] = t[2]; bl[2*pr+1][1] = t[3];
            }
            #pragma unroll
            for (int mi = 0; mi < 2; mi++) {
                #pragma unroll
                for (int ni = 0; ni < 8; ni++) {
                    mma16816(acc[mi][ni], ah[mi], bh[ni]);
                    mma16816(acc[mi][ni], ah[mi], bl[ni]);
                }
            }
            uint32_t al[2][4];
            #pragma unroll
            for (int mi = 0; mi < 2; mi++) {
                ldm_x4(al[mi], smem_u32(&sA[1][wm * 32 + mi * 16 + arow][acol]));
            }
            #pragma unroll
            for (int mi = 0; mi < 2; mi++) {
                #pragma unroll
                for (int ni = 0; ni < 8; ni++) {
                    mma16816(acc[mi][ni], al[mi], bh[ni]);
                }
            }
        }
        __syncthreads();
    }

    int g = lane >> 2, tg = lane & 3;
    #pragma unroll
    for (int mi = 0; mi < 2; mi++) {
        #pragma unroll
        for (int ni = 0; ni < 8; ni++) {
            size_t row0 = (size_t)bm * 128 + wm * 32 + mi * 16 + g;
            size_t col  = (size_t)bn * 128 + wn * 64 + ni * 8 + tg * 2;
            float2 v0 = make_float2(acc[mi][ni][0], acc[mi][ni][1]);
            float2 v1 = make_float2(acc[mi][ni][2], acc[mi][ni][3]);
            if (WITH_ADD) {
                float2 a0 = *(const float2*)(ADD + row0 * N + col);
                float2 a1 = *(const float2*)(ADD + (row0 + 8) * N + col);
                v0.x += a0.x; v0.y += a0.y; v1.x += a1.x; v1.y += a1.y;
            }
            *(float2*)(C + row0 * N + col) = v0;
            *(float2*)(C + (row0 + 8) * N + col) = v1;
        }
    }
}

// ---------------- conv + silu + softplus(dt) + decay + dtx ----------------
__global__ void conv_dt_kernel(const float* __restrict__ conv_w,
                               const float* __restrict__ conv_b,
                               const float* __restrict__ A_log) {
    int row = blockIdx.x;
    int t = row & (LSEQ - 1);
    size_t base = (size_t)row * PROJ;

    for (int c = threadIdx.x; c < DINNER; c += 256) {
        float acc = conv_b[c];
        #pragma unroll
        for (int k = 0; k < 4; k++) {
            int tt = t - 3 + k;
            if (tt >= 0)
                acc = fmaf(conv_w[c * 4 + k], g_proj[base + (size_t)(k - 3) * PROJ + c], acc);
        }
        float xs = siluf(acc);
        int h = c >> 1;
        float dts = softplusf(g_proj[base + OFF_DT + h]);
        g_dtx[(size_t)row * DINNER + c] = dts * xs;
    }
    for (int h = threadIdx.x; h < HEADS; h += 256) {
        float dts = softplusf(g_proj[base + OFF_DT + h]);
        float A = -expf(A_log[h]);
        g_decay[(size_t)row * HEADS + h] = expf(dts * A);
    }
}

// ---------------- chunked selective scan ----------------
// Pass 1: per (bh, chunk), run zero-start recurrence over TCHUNK steps;
// store end-state (256 floats) and decay product.
// Block = 4 warps, same chunk, consecutive bh (B/C rows shared -> L1 reuse).
__global__ void __launch_bounds__(128) scan_pass1() {
    int blk   = blockIdx.x;
    int chunk = blk & (NCHUNK - 1);
    int bhg   = blk >> 4;
    int bh    = bhg * 4 + (threadIdx.x >> 5);
    int b     = bh >> 10;
    int h     = bh & (HEADS - 1);
    int lane  = threadIdx.x & 31;
    int p     = lane >> 4;
    int j0    = (lane & 15) * 8;

    float S[8];
    #pragma unroll
    for (int i = 0; i < 8; i++) S[i] = 0.f;
    float dprod = 1.f;

    size_t rowBase = (size_t)b * LSEQ + (size_t)chunk * TCHUNK;
    #pragma unroll 2
    for (int tt = 0; tt < TCHUNK; tt++) {
        size_t row = rowBase + tt;
        size_t pb  = row * PROJ;
        float dec = g_decay[row * HEADS + h];
        float cx  = g_dtx[row * DINNER + h * 2 + p];
        float4 b0 = *(const float4*)(g_proj + pb + OFF_B + j0);
        float4 b1 = *(const float4*)(g_proj + pb + OFF_B + j0 + 4);
        S[0] = fmaf(dec, S[0], cx * b0.x);
        S[1] = fmaf(dec, S[1], cx * b0.y);
        S[2] = fmaf(dec, S[2], cx * b0.z);
        S[3] = fmaf(dec, S[3], cx * b0.w);
        S[4] = fmaf(dec, S[4], cx * b1.x);
        S[5] = fmaf(dec, S[5], cx * b1.y);
        S[6] = fmaf(dec, S[6], cx * b1.z);
        S[7] = fmaf(dec, S[7], cx * b1.w);
        dprod *= dec;
    }

    size_t sbase = ((size_t)bh * NCHUNK + chunk) * 256 + p * 128 + j0;
    *(float4*)(g_state + sbase)     = make_float4(S[0], S[1], S[2], S[3]);
    *(float4*)(g_state + sbase + 4) = make_float4(S[4], S[5], S[6], S[7]);
    if (lane == 0) g_dprod[bh * NCHUNK + chunk] = dprod;
}

// Pass 2: in-place convert chunk end-states -> chunk initial states.
// S_init(c) = D(c-1)*S_init(c-1) + S_loc(c-1), S_init(0)=0.
__global__ void __launch_bounds__(256) scan_pass2() {
    int bh = blockIdx.x;
    int s  = threadIdx.x;   // 0..255 state slot
    float run = 0.f;
    size_t base = (size_t)bh * NCHUNK * 256 + s;
    #pragma unroll
    for (int c = 0; c < NCHUNK; c++) {
        float v = g_state[base + (size_t)c * 256];
        float D = g_dprod[bh * NCHUNK + c];
        g_state[base + (size_t)c * 256] = run;
        run = fmaf(D, run, v);
    }
}

// Pass 3: replay each chunk from its true initial state, compute y + gate.
__global__ void __launch_bounds__(128) scan_pass3() {
    int blk   = blockIdx.x;
    int chunk = blk & (NCHUNK - 1);
    int bhg   = blk >> 4;
    int bh    = bhg * 4 + (threadIdx.x >> 5);
    int b     = bh >> 10;
    int h     = bh & (HEADS - 1);
    int lane  = threadIdx.x & 31;
    int p     = lane >> 4;
    int j0    = (lane & 15) * 8;

    size_t sbase = ((size_t)bh * NCHUNK + chunk) * 256 + p * 128 + j0;
    float4 si0 = *(const float4*)(g_state + sbase);
    float4 si1 = *(const float4*)(g_state + sbase + 4);
    float S[8] = {si0.x, si0.y, si0.z, si0.w, si1.x, si1.y, si1.z, si1.w};

    size_t rowBase = (size_t)b * LSEQ + (size_t)chunk * TCHUNK;
    #pragma unroll 2
    for (int tt = 0; tt < TCHUNK; tt++) {
        size_t row = rowBase + tt;
        size_t pb  = row * PROJ;
        float dec = g_decay[row * HEADS + h];
        float cx  = g_dtx[row * DINNER + h * 2 + p];
        float4 b0 = *(const float4*)(g_proj + pb + OFF_B + j0);
        float4 b1 = *(const float4*)(g_proj + pb + OFF_B + j0 + 4);
        float4 c0 = *(const float4*)(g_proj + pb + OFF_C + j0);
        float4 c1 = *(const float4*)(g_proj + pb + OFF_C + j0 + 4);

        float y = 0.f;
        S[0] = fmaf(dec, S[0], cx * b0.x); y = fmaf(S[0], c0.x, y);
        S[1] = fmaf(dec, S[1], cx * b0.y); y = fmaf(S[1], c0.y, y);
        S[2] = fmaf(dec, S[2], cx * b0.z); y = fmaf(S[2], c0.z, y);
        S[3] = fmaf(dec, S[3], cx * b0.w); y = fmaf(S[3], c0.w, y);
        S[4] = fmaf(dec, S[4], cx * b1.x); y = fmaf(S[4], c1.x, y);
        S[5] = fmaf(dec, S[5], cx * b1.y); y = fmaf(S[5], c1.y, y);
        S[6] = fmaf(dec, S[6], cx * b1.z); y = fmaf(S[6], c1.z, y);
        S[7] = fmaf(dec, S[7], cx * b1.w); y = fmaf(S[7], c1.w, y);

        y += __shfl_xor_sync(0xffffffffu, y, 1);
        y += __shfl_xor_sync(0xffffffffu, y, 2);
        y += __shfl_xor_sync(0xffffffffu, y, 4);
        y += __shfl_xor_sync(0xffffffffu, y, 8);

        if ((lane & 15) == 0) {
            float z = g_proj[pb + OFF_Z + h * 2 + p];
            float gv = y * siluf(z);
            __nv_bfloat16 hi, lo;
            split_bf16(gv, hi, lo);
            size_t idx = row * DINNER + h * 2 + p;
            g_gate_h[idx] = hi;
            g_gate_l[idx] = lo;
        }
    }
}

// ---------------- launch ----------------
extern "C" void kernel_launch(void* const* d_in, const int* in_sizes, int n_in,
                              void* d_out, int out_size) {
    const float* u      = (const float*)d_in[0];
    const float* W_in   = (const float*)d_in[1];
    const float* conv_w = (const float*)d_in[2];
    const float* conv_b = (const float*)d_in[3];
    const float* W_out  = (const float*)d_in[4];
    const float* ln_g   = (const float*)d_in[5];
    const float* ln_b   = (const float*)d_in[6];
    const float* A_log  = (const float*)d_in[7];
    float* out = (float*)d_out;

    float* p_proj;
    __nv_bfloat16 *p_xn_h, *p_xn_l, *p_gate_h, *p_gate_l;
    __nv_bfloat16 *p_win_h, *p_win_l, *p_wout_h, *p_wout_l;
    cudaGetSymbolAddress((void**)&p_proj,   g_proj);
    cudaGetSymbolAddress((void**)&p_xn_h,   g_xn_h);
    cudaGetSymbolAddress((void**)&p_xn_l,   g_xn_l);
    cudaGetSymbolAddress((void**)&p_gate_h, g_gate_h);
    cudaGetSymbolAddress((void**)&p_gate_l, g_gate_l);
    cudaGetSymbolAddress((void**)&p_win_h,  g_win_h);
    cudaGetSymbolAddress((void**)&p_win_l,  g_win_l);
    cudaGetSymbolAddress((void**)&p_wout_h, g_wout_h);
    cudaGetSymbolAddress((void**)&p_wout_l, g_wout_l);

    // weight splits
    {
        int n1 = DMODEL * PROJ;
        split_kernel<<<(n1 + 255) / 256, 256>>>(W_in, p_win_h, p_win_l, n1);
        int n2 = DINNER * DMODEL;
        split_kernel<<<(n2 + 255) / 256, 256>>>(W_out, p_wout_h, p_wout_l, n2);
    }

    // 1. layernorm -> bf16 hi/lo
    ln_kernel<<<ROWS, 256>>>(u, ln_g, ln_b);

    // 2. proj = xn @ W_in : (4096,1024)@(1024,5376)
    {
        dim3 grid(PROJ / 128, ROWS / 128);
        gemm_bf16<0><<<grid, 256>>>(p_xn_h, p_xn_l, p_win_h, p_win_l,
                                    p_proj, nullptr, ROWS, PROJ, DMODEL);
    }

    // 3. conv + dt/decay/dtx
    conv_dt_kernel<<<ROWS, 256>>>(conv_w, conv_b, A_log);

    // 4. chunked selective scan + gating -> bf16 hi/lo
    {
        int blocks = (BATCH * HEADS / 4) * NCHUNK;   // 8192
        scan_pass1<<<blocks, 128>>>();
        scan_pass2<<<BATCH * HEADS, 256>>>();
        scan_pass3<<<blocks, 128>>>();
    }

    // 5. out = u + gate @ W_out : (4096,2048)@(2048,1024)
    {
        dim3 grid(DMODEL / 128, ROWS / 128);
        gemm_bf16<1><<<grid, 256>>>(p_gate_h, p_gate_l, p_wout_h, p_wout_l,
                                    out, u, ROWS, DMODEL, DINNER);
    }
}